// round 5
// baseline (speedup 1.0000x reference)
#include <cuda_runtime.h>

#define N_VOX 1000000
#define KVOL  27
#define C_IN  3
#define C_HID 64
#define C_OUT 3
#define BN_EPS 1e-5f
#define PTS   4          // points per thread (conv1)
#define TPB   256
#define PPB   (PTS*TPB)

// Scratch (device globals: allocation-free per harness rules)
__device__ float g_h[(size_t)N_VOX * C_HID];   // 256 MB: conv1 out, then BN+ReLU in-place
__device__ float g_stats[4 * C_HID];           // sum, sumsq, scale, shift

typedef unsigned long long u64;

__device__ __forceinline__ u64 pack2(float lo, float hi) {
    u64 r; asm("mov.b64 %0, {%1, %2};" : "=l"(r) : "f"(lo), "f"(hi)); return r;
}
__device__ __forceinline__ void unpack2(u64 v, float& lo, float& hi) {
    asm("mov.b64 {%0, %1}, %2;" : "=f"(lo), "=f"(hi) : "l"(v));
}
#define FMA2(d, a, b, c) asm("fma.rn.f32x2 %0, %1, %2, %3;" : "=l"(d) : "l"(a), "l"(b), "l"(c))

// ---------------------------------------------------------------------------
__global__ void zero_stats_kernel() {
    int i = threadIdx.x;
    if (i < 2 * C_HID) g_stats[i] = 0.f;
}
__global__ void dummy_kernel() {}   // keeps conv1 at ncu capture index 3

// ---------------------------------------------------------------------------
// conv1: h[n,:] = sum_k feats[nbr[k,n]] @ W1[k]
// 4 points/thread, 4 channel-chunks of 16 (8 pairs): weight LDS amortized 4x.
__global__ __launch_bounds__(TPB) void conv1_kernel(const float* __restrict__ feats,
                                                    const float* __restrict__ W1,
                                                    const int*   __restrict__ nbr) {
    __shared__ u64 w1s[KVOL * C_IN * C_HID / 2];   // [k][c][pair]
    {
        const u64* w1g = (const u64*)W1;
        for (int i = threadIdx.x; i < KVOL * C_IN * C_HID / 2; i += TPB) w1s[i] = w1g[i];
    }
    __syncthreads();
    const int base = blockIdx.x * PPB + threadIdx.x;

    #pragma unroll 1
    for (int chunk = 0; chunk < 4; chunk++) {
        u64 acc[PTS][8];
        #pragma unroll
        for (int i = 0; i < PTS; i++)
            #pragma unroll
            for (int p = 0; p < 8; p++) acc[i][p] = 0ull;

        #pragma unroll 1
        for (int k = 0; k < KVOL; k++) {
            float f[PTS][3];
            #pragma unroll
            for (int i = 0; i < PTS; i++) {
                int n = base + i * TPB;
                int idx = (n < N_VOX) ? __ldg(&nbr[(size_t)k * N_VOX + n]) : -1;
                if (idx >= 0) {
                    f[i][0] = __ldg(&feats[3 * idx + 0]);
                    f[i][1] = __ldg(&feats[3 * idx + 1]);
                    f[i][2] = __ldg(&feats[3 * idx + 2]);
                } else {
                    f[i][0] = 0.f; f[i][1] = 0.f; f[i][2] = 0.f;
                }
            }
            const u64* w = w1s + k * 96 + chunk * 8;
            #pragma unroll
            for (int i = 0; i < PTS; i++) {
                u64 a0 = pack2(f[i][0], f[i][0]);
                u64 a1 = pack2(f[i][1], f[i][1]);
                u64 a2 = pack2(f[i][2], f[i][2]);
                #pragma unroll
                for (int p = 0; p < 8; p++) {
                    FMA2(acc[i][p], a0, w[p],      acc[i][p]);
                    FMA2(acc[i][p], a1, w[32 + p], acc[i][p]);
                    FMA2(acc[i][p], a2, w[64 + p], acc[i][p]);
                }
            }
        }
        #pragma unroll
        for (int i = 0; i < PTS; i++) {
            int n = base + i * TPB;
            if (n < N_VOX) {
                ulonglong2* ho = (ulonglong2*)(g_h + (size_t)n * C_HID + chunk * 16);
                #pragma unroll
                for (int j = 0; j < 4; j++)
                    ho[j] = make_ulonglong2(acc[i][2 * j], acc[i][2 * j + 1]);
            }
        }
    }
}

// ---------------------------------------------------------------------------
// BN stats: per-channel sum / sumsq over all N rows of g_h
__global__ __launch_bounds__(256) void stats_kernel() {
    int d = threadIdx.x & 63;
    int r = threadIdx.x >> 6;
    float s = 0.f, s2 = 0.f;
    for (size_t n = (size_t)blockIdx.x * 4 + r; n < N_VOX; n += (size_t)gridDim.x * 4) {
        float v = g_h[n * C_HID + d];
        s += v; s2 += v * v;
    }
    __shared__ float sm[8][C_HID];
    sm[r][d] = s; sm[4 + r][d] = s2;
    __syncthreads();
    if (r == 0) {
        s  = sm[0][d] + sm[1][d] + sm[2][d] + sm[3][d];
        s2 = sm[4][d] + sm[5][d] + sm[6][d] + sm[7][d];
        atomicAdd(&g_stats[d], s);
        atomicAdd(&g_stats[C_HID + d], s2);
    }
}

__global__ void finalize_kernel(const float* __restrict__ gamma,
                                const float* __restrict__ beta) {
    int d = threadIdx.x;
    if (d < C_HID) {
        float mu  = g_stats[d] * (1.f / N_VOX);
        float var = g_stats[C_HID + d] * (1.f / N_VOX) - mu * mu;
        float sc  = gamma[d] * rsqrtf(var + BN_EPS);
        g_stats[2 * C_HID + d] = sc;
        g_stats[3 * C_HID + d] = beta[d] - mu * sc;
    }
}

// ---------------------------------------------------------------------------
// BN + ReLU applied in-place to g_h (safe: conv1 rewrites g_h every replay)
__global__ __launch_bounds__(256) void bnrelu_kernel() {
    __shared__ float scs[C_HID], shs[C_HID];
    if (threadIdx.x < C_HID) {
        scs[threadIdx.x] = g_stats[2 * C_HID + threadIdx.x];
        shs[threadIdx.x] = g_stats[3 * C_HID + threadIdx.x];
    }
    __syncthreads();
    const size_t total = (size_t)N_VOX * (C_HID / 4);
    float4* h4 = (float4*)g_h;
    for (size_t e = (size_t)blockIdx.x * 256 + threadIdx.x; e < total;
         e += (size_t)gridDim.x * 256) {
        int j = (int)(e & 15);
        float4 v = h4[e];
        v.x = fmaxf(fmaf(v.x, scs[4 * j + 0], shs[4 * j + 0]), 0.f);
        v.y = fmaxf(fmaf(v.y, scs[4 * j + 1], shs[4 * j + 1]), 0.f);
        v.z = fmaxf(fmaf(v.z, scs[4 * j + 2], shs[4 * j + 2]), 0.f);
        v.w = fmaxf(fmaf(v.w, scs[4 * j + 3], shs[4 * j + 3]), 0.f);
        h4[e] = v;
    }
}

// ---------------------------------------------------------------------------
// conv2 (fused): out[n] = sum_k valid * ( hact[nbr[k,n]] @ W2[26-k] )
// 16-lane teams own one point each; validity compressed into a 27-bit mask per
// point so the inner loop runs only over valid k (~4.7 avg, warp ~max 6.5).
#define PBLK 128
__global__ __launch_bounds__(256) void conv2_kernel(const float* __restrict__ W2,
                                                    const int*   __restrict__ nbr,
                                                    float* __restrict__ out) {
    __shared__ u64 w2t[KVOL * C_OUT * C_HID / 2];   // [k][c][pair], k -> W2[26-k]
    __shared__ int idxs[KVOL * PBLK];
    __shared__ unsigned msk[PBLK];
    const int tid = threadIdx.x;
    {
        float* w2tf = (float*)w2t;
        for (int i = tid; i < KVOL * C_OUT * C_HID; i += 256) {
            int kk  = i / (C_OUT * C_HID);
            int rem = i % (C_OUT * C_HID);
            int c   = rem / C_HID;
            int d   = rem % C_HID;
            w2tf[(kk * C_OUT + c) * C_HID + d] =
                W2[(size_t)(KVOL - 1 - kk) * (C_HID * C_OUT) + d * C_OUT + c];
        }
    }
    const int base = blockIdx.x * PBLK;
    for (int i = tid; i < KVOL * PBLK; i += 256) {
        int k = i / PBLK, pl = i % PBLK;
        int n = base + pl;
        idxs[i] = (n < N_VOX) ? __ldg(&nbr[(size_t)k * N_VOX + n]) : -1;
    }
    __syncthreads();
    if (tid < PBLK) {
        unsigned m = 0;
        #pragma unroll
        for (int k = 0; k < KVOL; k++)
            if (idxs[k * PBLK + tid] >= 0) m |= (1u << k);
        msk[tid] = m;
    }
    __syncthreads();

    const int lane  = tid & 31;
    const int wrp   = tid >> 5;
    const int tlane = lane & 15;
    const int half  = lane >> 4;

    #pragma unroll 1
    for (int pp = 0; pp < PBLK / 16; pp++) {       // 8 point-pairs per warp
        const int pl = (wrp * (PBLK / 16) + pp) * 2 + half;
        const int n  = base + pl;

        u64 acc0 = 0ull, acc1 = 0ull, acc2 = 0ull;
        unsigned m = msk[pl];
        while (m) {
            int k = __ffs(m) - 1;
            m &= m - 1;
            int id = idxs[k * PBLK + pl];
            ulonglong2 hv = __ldg((const ulonglong2*)(g_h + (size_t)id * C_HID) + tlane);
            const ulonglong2* wb = (const ulonglong2*)(w2t + k * 96 + 2 * tlane);
            ulonglong2 w0 = wb[0], w1 = wb[16], w2v = wb[32];
            FMA2(acc0, hv.x, w0.x,  acc0); FMA2(acc0, hv.y, w0.y,  acc0);
            FMA2(acc1, hv.x, w1.x,  acc1); FMA2(acc1, hv.y, w1.y,  acc1);
            FMA2(acc2, hv.x, w2v.x, acc2); FMA2(acc2, hv.y, w2v.y, acc2);
        }
        float r0, r1, r2;
        { float lo, hi; unpack2(acc0, lo, hi); r0 = lo + hi; }
        { float lo, hi; unpack2(acc1, lo, hi); r1 = lo + hi; }
        { float lo, hi; unpack2(acc2, lo, hi); r2 = lo + hi; }
        #pragma unroll
        for (int o = 8; o >= 1; o >>= 1) {
            r0 += __shfl_xor_sync(0xffffffffu, r0, o);
            r1 += __shfl_xor_sync(0xffffffffu, r1, o);
            r2 += __shfl_xor_sync(0xffffffffu, r2, o);
        }
        if (tlane == 0 && n < N_VOX) {
            out[3 * n + 0] = r0;
            out[3 * n + 1] = r1;
            out[3 * n + 2] = r2;
        }
    }
}

// ---------------------------------------------------------------------------
extern "C" void kernel_launch(void* const* d_in, const int* in_sizes, int n_in,
                              void* d_out, int out_size) {
    const float* feats = (const float*)d_in[0];
    const float* W1    = (const float*)d_in[1];
    const float* gamma = (const float*)d_in[2];
    const float* beta  = (const float*)d_in[3];
    const float* W2    = (const float*)d_in[4];
    const int*   nbr   = (const int*)  d_in[5];
    float*       out   = (float*)d_out;

    zero_stats_kernel<<<1, 128>>>();                               // 0
    dummy_kernel<<<1, 32>>>();                                     // 1
    dummy_kernel<<<1, 32>>>();                                     // 2
    conv1_kernel<<<(N_VOX + PPB - 1) / PPB, TPB>>>(feats, W1, nbr); // 3 <- ncu
    stats_kernel<<<2048, 256>>>();                                 // 4
    finalize_kernel<<<1, 64>>>(gamma, beta);                       // 5
    bnrelu_kernel<<<4096, 256>>>();                                // 6
    conv2_kernel<<<(N_VOX + PBLK - 1) / PBLK, 256>>>(W2, nbr, out); // 7
}

// round 6
// speedup vs baseline: 1.9469x; 1.9469x over previous
#include <cuda_runtime.h>

#define N_VOX 1000000
#define KVOL  27
#define C_IN  3
#define C_HID 64
#define C_OUT 3
#define BN_EPS 1e-5f
#define PBLK  128   // points per block (256 thr = 16 teams, 8 pts/team)

// Scratch (device globals: allocation-free per harness rules)
__device__ float g_h[(size_t)N_VOX * C_HID];   // 256 MB: conv1 out (pre-BN)
__device__ float g_stats[4 * C_HID];           // sum, sumsq, scale, shift

typedef unsigned long long u64;

__device__ __forceinline__ u64 pack2(float lo, float hi) {
    u64 r; asm("mov.b64 %0, {%1, %2};" : "=l"(r) : "f"(lo), "f"(hi)); return r;
}
__device__ __forceinline__ void unpack2(u64 v, float& lo, float& hi) {
    asm("mov.b64 {%0, %1}, %2;" : "=f"(lo), "=f"(hi) : "l"(v));
}
#define FMA2(d, a, b, c) asm("fma.rn.f32x2 %0, %1, %2, %3;" : "=l"(d) : "l"(a), "l"(b), "l"(c))

__device__ __forceinline__ u64 relu2(u64 v) {
    float a, b; unpack2(v, a, b);
    return pack2(fmaxf(a, 0.f), fmaxf(b, 0.f));
}

// ---------------------------------------------------------------------------
__global__ void zero_stats_kernel() {
    int i = threadIdx.x;
    if (i < 2 * C_HID) g_stats[i] = 0.f;
}
__global__ void dummy_kernel() {}   // keeps conv1 at ncu capture index 3

// ---------------------------------------------------------------------------
// conv1 (team-sparse): h[n,:] = sum_{valid k} feats[nbr[k,n]] @ W1[k]
// 16-lane teams own one point; lane owns channels 4t..4t+3 (pairs 2t,2t+1).
// Masked loop visits only valid k (~4.7 avg). Fused BN-stats accumulation.
__global__ __launch_bounds__(256) void conv1_kernel(const float* __restrict__ feats,
                                                    const float* __restrict__ W1,
                                                    const int*   __restrict__ nbr) {
    __shared__ u64 w1s[KVOL * C_IN * C_HID / 2];   // [k][c][pair], 20.7 KB
    __shared__ int idxs[KVOL * PBLK];              // 13.8 KB
    __shared__ unsigned msk[PBLK];
    __shared__ float sm_s[8][C_HID], sm_s2[8][C_HID];
    const int tid = threadIdx.x;
    {
        const u64* w1g = (const u64*)W1;
        for (int i = tid; i < KVOL * C_IN * C_HID / 2; i += 256) w1s[i] = w1g[i];
    }
    const int base = blockIdx.x * PBLK;
    for (int i = tid; i < KVOL * PBLK; i += 256) {
        int k = i / PBLK, pl = i % PBLK;
        int n = base + pl;
        idxs[i] = (n < N_VOX) ? __ldg(&nbr[(size_t)k * N_VOX + n]) : -1;
    }
    __syncthreads();
    if (tid < PBLK) {
        unsigned m = 0;
        #pragma unroll
        for (int k = 0; k < KVOL; k++)
            if (idxs[k * PBLK + tid] >= 0) m |= (1u << k);
        msk[tid] = m;
    }
    __syncthreads();

    const int lane  = tid & 31;
    const int wrp   = tid >> 5;
    const int tlane = lane & 15;
    const int half  = lane >> 4;

    float s0 = 0.f, s1 = 0.f, s2v = 0.f, s3 = 0.f;
    float q0 = 0.f, q1 = 0.f, q2 = 0.f, q3 = 0.f;

    #pragma unroll 1
    for (int pp = 0; pp < PBLK / 16; pp++) {        // 8 point-pairs per warp
        const int pl = (wrp * (PBLK / 16) + pp) * 2 + half;
        const int n  = base + pl;

        u64 acc0 = 0ull, acc1 = 0ull;               // channels 4t..4t+3
        unsigned m = msk[pl];
        while (m) {
            int k = __ffs(m) - 1;
            m &= m - 1;
            int id = idxs[k * PBLK + pl];
            float f0 = __ldg(&feats[3 * id + 0]);
            float f1 = __ldg(&feats[3 * id + 1]);
            float f2 = __ldg(&feats[3 * id + 2]);
            const ulonglong2* wb = (const ulonglong2*)(w1s + k * 96 + 2 * tlane);
            ulonglong2 w0 = wb[0], w1v = wb[16], w2v = wb[32];
            u64 a0 = pack2(f0, f0), a1 = pack2(f1, f1), a2 = pack2(f2, f2);
            FMA2(acc0, a0, w0.x,  acc0); FMA2(acc1, a0, w0.y,  acc1);
            FMA2(acc0, a1, w1v.x, acc0); FMA2(acc1, a1, w1v.y, acc1);
            FMA2(acc0, a2, w2v.x, acc0); FMA2(acc1, a2, w2v.y, acc1);
        }
        if (n < N_VOX) {
            ulonglong2* ho = (ulonglong2*)(g_h + (size_t)n * C_HID) + tlane;
            *ho = make_ulonglong2(acc0, acc1);
            float h0, h1, h2, h3;
            unpack2(acc0, h0, h1);
            unpack2(acc1, h2, h3);
            s0 += h0; s1 += h1; s2v += h2; s3 += h3;
            q0 = fmaf(h0, h0, q0); q1 = fmaf(h1, h1, q1);
            q2 = fmaf(h2, h2, q2); q3 = fmaf(h3, h3, q3);
        }
    }

    // stats reduction: lane^16 shares the same channel set
    s0 += __shfl_xor_sync(0xffffffffu, s0, 16);
    s1 += __shfl_xor_sync(0xffffffffu, s1, 16);
    s2v += __shfl_xor_sync(0xffffffffu, s2v, 16);
    s3 += __shfl_xor_sync(0xffffffffu, s3, 16);
    q0 += __shfl_xor_sync(0xffffffffu, q0, 16);
    q1 += __shfl_xor_sync(0xffffffffu, q1, 16);
    q2 += __shfl_xor_sync(0xffffffffu, q2, 16);
    q3 += __shfl_xor_sync(0xffffffffu, q3, 16);
    if (lane < 16) {
        sm_s [wrp][4 * tlane + 0] = s0;  sm_s [wrp][4 * tlane + 1] = s1;
        sm_s [wrp][4 * tlane + 2] = s2v; sm_s [wrp][4 * tlane + 3] = s3;
        sm_s2[wrp][4 * tlane + 0] = q0;  sm_s2[wrp][4 * tlane + 1] = q1;
        sm_s2[wrp][4 * tlane + 2] = q2;  sm_s2[wrp][4 * tlane + 3] = q3;
    }
    __syncthreads();
    if (tid < C_HID) {
        float t = 0.f, t2 = 0.f;
        #pragma unroll
        for (int w = 0; w < 8; w++) { t += sm_s[w][tid]; t2 += sm_s2[w][tid]; }
        atomicAdd(&g_stats[tid], t);
        atomicAdd(&g_stats[C_HID + tid], t2);
    }
}

// ---------------------------------------------------------------------------
__global__ void finalize_kernel(const float* __restrict__ gamma,
                                const float* __restrict__ beta) {
    int d = threadIdx.x;
    if (d < C_HID) {
        float mu  = g_stats[d] * (1.f / N_VOX);
        float var = g_stats[C_HID + d] * (1.f / N_VOX) - mu * mu;
        float sc  = gamma[d] * rsqrtf(var + BN_EPS);
        g_stats[2 * C_HID + d] = sc;
        g_stats[3 * C_HID + d] = beta[d] - mu * sc;
    }
}

// ---------------------------------------------------------------------------
// conv2 (fused): out[n] = sum_k valid * ( relu(bn(h[nbr[k,n]])) @ W2[26-k] )
// 16-lane teams, masked k loop, BN+ReLU applied in-register at gather time
// (lane-constant packed scale/shift).
__global__ __launch_bounds__(256) void conv2_kernel(const float* __restrict__ W2,
                                                    const int*   __restrict__ nbr,
                                                    float* __restrict__ out) {
    __shared__ u64 w2t[KVOL * C_OUT * C_HID / 2];   // [k][c][pair], k -> W2[26-k]
    __shared__ int idxs[KVOL * PBLK];
    __shared__ unsigned msk[PBLK];
    const int tid = threadIdx.x;
    {
        float* w2tf = (float*)w2t;
        for (int i = tid; i < KVOL * C_OUT * C_HID; i += 256) {
            int kk  = i / (C_OUT * C_HID);
            int rem = i % (C_OUT * C_HID);
            int c   = rem / C_HID;
            int d   = rem % C_HID;
            w2tf[(kk * C_OUT + c) * C_HID + d] =
                W2[(size_t)(KVOL - 1 - kk) * (C_HID * C_OUT) + d * C_OUT + c];
        }
    }
    const int base = blockIdx.x * PBLK;
    for (int i = tid; i < KVOL * PBLK; i += 256) {
        int k = i / PBLK, pl = i % PBLK;
        int n = base + pl;
        idxs[i] = (n < N_VOX) ? __ldg(&nbr[(size_t)k * N_VOX + n]) : -1;
    }
    __syncthreads();
    if (tid < PBLK) {
        unsigned m = 0;
        #pragma unroll
        for (int k = 0; k < KVOL; k++)
            if (idxs[k * PBLK + tid] >= 0) m |= (1u << k);
        msk[tid] = m;
    }
    __syncthreads();

    const int lane  = tid & 31;
    const int wrp   = tid >> 5;
    const int tlane = lane & 15;
    const int half  = lane >> 4;

    // BN scale/shift for this lane's 4 channels (packed for FMA2)
    const u64 scA = pack2(g_stats[2 * C_HID + 4 * tlane + 0], g_stats[2 * C_HID + 4 * tlane + 1]);
    const u64 scB = pack2(g_stats[2 * C_HID + 4 * tlane + 2], g_stats[2 * C_HID + 4 * tlane + 3]);
    const u64 shA = pack2(g_stats[3 * C_HID + 4 * tlane + 0], g_stats[3 * C_HID + 4 * tlane + 1]);
    const u64 shB = pack2(g_stats[3 * C_HID + 4 * tlane + 2], g_stats[3 * C_HID + 4 * tlane + 3]);

    #pragma unroll 1
    for (int pp = 0; pp < PBLK / 16; pp++) {        // 8 point-pairs per warp
        const int pl = (wrp * (PBLK / 16) + pp) * 2 + half;
        const int n  = base + pl;

        u64 acc0 = 0ull, acc1 = 0ull, acc2 = 0ull;
        unsigned m = msk[pl];
        while (m) {
            int k = __ffs(m) - 1;
            m &= m - 1;
            int id = idxs[k * PBLK + pl];
            ulonglong2 hv = __ldg((const ulonglong2*)(g_h + (size_t)id * C_HID) + tlane);
            FMA2(hv.x, hv.x, scA, shA);
            FMA2(hv.y, hv.y, scB, shB);
            hv.x = relu2(hv.x);
            hv.y = relu2(hv.y);
            const ulonglong2* wb = (const ulonglong2*)(w2t + k * 96 + 2 * tlane);
            ulonglong2 w0 = wb[0], w1 = wb[16], w2v = wb[32];
            FMA2(acc0, hv.x, w0.x,  acc0); FMA2(acc0, hv.y, w0.y,  acc0);
            FMA2(acc1, hv.x, w1.x,  acc1); FMA2(acc1, hv.y, w1.y,  acc1);
            FMA2(acc2, hv.x, w2v.x, acc2); FMA2(acc2, hv.y, w2v.y, acc2);
        }
        float r0, r1, r2;
        { float lo, hi; unpack2(acc0, lo, hi); r0 = lo + hi; }
        { float lo, hi; unpack2(acc1, lo, hi); r1 = lo + hi; }
        { float lo, hi; unpack2(acc2, lo, hi); r2 = lo + hi; }
        #pragma unroll
        for (int o = 8; o >= 1; o >>= 1) {
            r0 += __shfl_xor_sync(0xffffffffu, r0, o);
            r1 += __shfl_xor_sync(0xffffffffu, r1, o);
            r2 += __shfl_xor_sync(0xffffffffu, r2, o);
        }
        if (tlane == 0 && n < N_VOX) {
            out[3 * n + 0] = r0;
            out[3 * n + 1] = r1;
            out[3 * n + 2] = r2;
        }
    }
}

// ---------------------------------------------------------------------------
extern "C" void kernel_launch(void* const* d_in, const int* in_sizes, int n_in,
                              void* d_out, int out_size) {
    const float* feats = (const float*)d_in[0];
    const float* W1    = (const float*)d_in[1];
    const float* gamma = (const float*)d_in[2];
    const float* beta  = (const float*)d_in[3];
    const float* W2    = (const float*)d_in[4];
    const int*   nbr   = (const int*)  d_in[5];
    float*       out   = (float*)d_out;

    const int nblk = (N_VOX + PBLK - 1) / PBLK;

    zero_stats_kernel<<<1, 128>>>();                    // 0
    dummy_kernel<<<1, 32>>>();                          // 1
    dummy_kernel<<<1, 32>>>();                          // 2
    conv1_kernel<<<nblk, 256>>>(feats, W1, nbr);        // 3 <- ncu
    finalize_kernel<<<1, 64>>>(gamma, beta);            // 4
    conv2_kernel<<<nblk, 256>>>(W2, nbr, out);          // 5
}